// round 12
// baseline (speedup 1.0000x reference)
#include <cuda_runtime.h>
#include <cuda_bf16.h>

#define BB 4
#define CC 64
#define HH 128
#define WW 128
#define HWW (HH*WW)
#define NPIX (BB*HH*WW)

#define DCN_PX 64
#define PT 68                      // sample-buffer row pitch (floats)
#define NTILES (NPIX/DCN_PX)       // 1024
#define DCN_GRID 296

// Scratch (allocation-free rule: device globals)
__device__ float g_xt[BB*HH*WW*CC];       // NHWC input (for dcn gathers)
__device__ float g_off[NPIX*20];          // offsets, pitch 20
__device__ float g_wt[9*64*64];           // dcn weights [k][c][o]
__device__ float g_owt[9*64*20];          // offset-conv weights [k][c][20]
__device__ float g_mean[CC];
__device__ float g_istd[CC];
__device__ float2 g_part[DCN_GRID*64];    // fused bnstats partials
__device__ int   g_tile_ctr;              // dynamic tile counter

// ---------------- packed f32x2 helpers ----------------
__device__ __forceinline__ unsigned long long splat2(float x) {
    unsigned long long r;
    asm("mov.b64 %0, {%1, %1};" : "=l"(r) : "f"(x));
    return r;
}
__device__ __forceinline__ unsigned long long pack2(float x, float y) {
    unsigned long long r;
    asm("mov.b64 %0, {%1, %2};" : "=l"(r) : "f"(x), "f"(y));
    return r;
}
__device__ __forceinline__ unsigned long long fma2(unsigned long long a,
                                                   unsigned long long b,
                                                   unsigned long long c) {
    unsigned long long d;
    asm("fma.rn.f32x2 %0, %1, %2, %3;" : "=l"(d) : "l"(a), "l"(b), "l"(c));
    return d;
}
__device__ __forceinline__ unsigned long long mul2(unsigned long long a,
                                                   unsigned long long b) {
    unsigned long long d;
    asm("mul.rn.f32x2 %0, %1, %2;" : "=l"(d) : "l"(a), "l"(b));
    return d;
}
__device__ __forceinline__ unsigned long long add2(unsigned long long a,
                                                   unsigned long long b) {
    unsigned long long d;
    asm("add.rn.f32x2 %0, %1, %2;" : "=l"(d) : "l"(a), "l"(b));
    return d;
}
__device__ __forceinline__ float2 unpk2(unsigned long long v) {
    float2 f;
    asm("mov.b64 {%0, %1}, %2;" : "=f"(f.x), "=f"(f.y) : "l"(v));
    return f;
}

// ---------------------------------------------------------------------------
// Kernel P: one-time weight transposes + tile-counter reset.
// ---------------------------------------------------------------------------
__global__ void k_prep(const float* __restrict__ dw, const float* __restrict__ ow) {
    int idx = blockIdx.x * 256 + threadIdx.x;
    if (idx == 0) g_tile_ctr = 0;
    if (idx < 9*64*64) {
        int k = idx / 4096;
        int r = idx % 4096;
        int c = r / 64;
        int o = r % 64;
        g_wt[idx] = dw[(o*64 + c)*9 + k];
    } else {
        int j = idx - 9*64*64;
        if (j < 9*64*20) {
            int k = j / 1280;
            int r = j % 1280;
            int c = r / 20;
            int o = r % 20;
            g_owt[j] = (o < 18) ? ow[(o*64 + c)*9 + k] : 0.f;
        }
    }
}

// ---------------------------------------------------------------------------
// Kernel 1: offset conv 3x3, 64 -> 18ch. Reads NCHW x (coalesced).
// ALSO emits the NHWC transpose g_xt for its own 2 rows (from staged tiles).
// ---------------------------------------------------------------------------
__global__ __launch_bounds__(256) void k_offconv(const float* __restrict__ x,
                                                 const float* __restrict__ ob) {
    extern __shared__ float sm[];
    float* sOW = sm;                 // 11520 floats
    float* xt  = sm + 11520;         // 8192 floats

    int tid = threadIdx.x;
    for (int i4 = tid; i4 < 2880; i4 += 256)
        ((float4*)sOW)[i4] = ((const float4*)g_owt)[i4];

    int b  = blockIdx.x >> 6;
    int y0 = (blockIdx.x & 63) * 2;
    int py = tid >> 7;               // 0..1
    int w  = tid & 127;
    int pid = b * HWW + (y0 + py) * WW + w;

    unsigned long long acc[9];
    #pragma unroll
    for (int j = 0; j < 9; j++) acc[j] = pack2(__ldg(ob + 2*j), __ldg(ob + 2*j + 1));

    #pragma unroll 1
    for (int cc = 0; cc < 4; cc++) {
        __syncthreads();
        #pragma unroll
        for (int j = 0; j < 8; j++) {
            int i4 = tid + j * 256;
            int ci = i4 >> 7;
            int r  = (i4 >> 5) & 3;
            int w4 = i4 & 31;
            int yr = y0 - 1 + r;
            float4 v = make_float4(0.f, 0.f, 0.f, 0.f);
            if (yr >= 0 && yr < HH)
                v = *((const float4*)(x + ((b*64 + cc*16 + ci)*HH + yr)*WW) + w4);
            ((float4*)xt)[i4] = v;
        }
        __syncthreads();

        #pragma unroll
        for (int ki = 0; ki < 3; ki++) {
            int r = py + ki;
            #pragma unroll
            for (int kj = 0; kj < 3; kj++) {
                int xx = w - 1 + kj;
                if (xx < 0 || xx >= WW) continue;
                const float* wk0 = sOW + ((ki*3 + kj)*64 + cc*16) * 20;
                const float* xr = xt + r*128 + xx;
                #pragma unroll 4
                for (int ci = 0; ci < 16; ci++) {
                    unsigned long long s2 = splat2(xr[ci * 512]);
                    const float* wr = wk0 + ci * 20;
                    const ulonglong2* w2 = (const ulonglong2*)wr;
                    ulonglong2 wa = w2[0];
                    ulonglong2 wb = w2[1];
                    unsigned long long wc = *(const unsigned long long*)(wr + 16);
                    acc[0] = fma2(s2, wa.x, acc[0]);
                    acc[1] = fma2(s2, wa.y, acc[1]);
                    acc[2] = fma2(s2, wb.x, acc[2]);
                    acc[3] = fma2(s2, wb.y, acc[3]);
                    acc[8] = fma2(s2, wc,   acc[8]);
                    const ulonglong2* w3 = (const ulonglong2*)(wr + 8);
                    ulonglong2 wd = w3[0];
                    ulonglong2 we = w3[1];
                    acc[4] = fma2(s2, wd.x, acc[4]);
                    acc[5] = fma2(s2, wd.y, acc[5]);
                    acc[6] = fma2(s2, we.x, acc[6]);
                    acc[7] = fma2(s2, we.y, acc[7]);
                }
            }
        }

        // ---- NHWC transpose emit for this pixel's 16 channels of chunk cc ----
        {
            const float* xc = xt + (py + 1) * 128 + w;   // center row = y0+py
            float4 o0 = make_float4(xc[0*512], xc[1*512], xc[2*512],  xc[3*512]);
            float4 o1 = make_float4(xc[4*512], xc[5*512], xc[6*512],  xc[7*512]);
            float4 o2 = make_float4(xc[8*512], xc[9*512], xc[10*512], xc[11*512]);
            float4 o3 = make_float4(xc[12*512],xc[13*512],xc[14*512], xc[15*512]);
            float4* dst = (float4*)(g_xt + (size_t)pid * 64 + cc * 16);
            dst[0] = o0; dst[1] = o1; dst[2] = o2; dst[3] = o3;
        }
    }
    float2* op = (float2*)(g_off + pid * 20);
    #pragma unroll
    for (int j = 0; j < 9; j++) op[j] = unpk2(acc[j]);
}

// ---------------------------------------------------------------------------
// Kernel 2: deformable sampling + DCN conv. Persistent + dynamic stealing.
// Two-set gather pipelining (aA/aB): LDG->consume distance = 2 compute groups.
// BN accumulators moved to padded smem (sBN) to fund the extra a-set regs.
// smem map: sS 0..34816 | sWb/sRed 34816..67584 | sPI 67584..76800 |
//           sPF 76800..86016 | sT 86016..86032 | sBN 86032..90384
// ---------------------------------------------------------------------------
__global__ __launch_bounds__(256, 2) void k_dcn(float* __restrict__ out) {
    extern __shared__ char smem[];
    float*  sS  = (float*)smem;                     // [2][64][PT]
    float*  sWb = (float*)(smem + 34816);           // [2][4096]
    float*  sRed = (float*)(smem + 34816);          // reduce region (reuses sWb)
    int4*   sPI = (int4*)(smem + 67584);            // [9*64]
    float4* sPF = (float4*)(smem + 76800);          // [9*64]
    volatile int* sT = (volatile int*)(smem + 86016);  // [2] tile ids
    float*  sBN = (float*)(smem + 86032);           // [64][17] BN partials

    const int tid = threadIdx.x;
    // gather mapping
    const int q   = tid & 15;          // channel chunk (4 c's)
    const int sub = tid >> 4;          // pixel-within-pass
    // compute mapping
    const int lane = tid & 31;
    const int wid  = tid >> 5;
    const int Q    = wid & 1;          // o half
    const int ch   = wid >> 1;         // c quarter (16 c's)
    const int pg   = lane & 7;         // pixel quad
    const int osub = (lane >> 3) & 3;
    const int obase = 32*Q + 8*osub;   // 8 o's per thread

    auto stage_w = [&](int k, int buf) {
        const float* src = g_wt + k * 4096 + tid * 4;
        unsigned dst = (unsigned)__cvta_generic_to_shared(sWb + buf * 4096 + tid * 4);
        #pragma unroll
        for (int j = 0; j < 4; j++) {
            asm volatile("cp.async.cg.shared.global [%0], [%1], 16;"
                         :: "r"(dst + j * 4096), "l"(src + j * 1024) : "memory");
        }
        asm volatile("cp.async.commit_group;" ::: "memory");
    };

    // zero BN smem accumulators
    if (tid < 64) {
        #pragma unroll
        for (int j = 0; j < 16; j++) sBN[tid * 17 + j] = 0.f;
    }

    // first tile fetch
    if (tid == 0) sT[0] = atomicAdd(&g_tile_ctr, 1);
    int pr = 0;

    while (true) {
        __syncthreads();   // orders sT/sBN writes + previous tile's work
        const int t = sT[pr];
        if (t >= NTILES) break;
        if (tid == 0) sT[pr ^ 1] = atomicAdd(&g_tile_ctr, 1);
        pr ^= 1;

        const int pixbase = t * DCN_PX;

        stage_w(0, 0);     // overlap with params computation below

        // ---- sampling params for all (k, px) ----
        for (int tt = tid; tt < 9 * DCN_PX; tt += 256) {
            int k  = tt / DCN_PX;
            int px = tt % DCN_PX;
            int pid = pixbase + px;
            int rem = pid & (HWW - 1);
            int h   = rem / WW;
            int w   = rem % WW;
            int ki = k / 3, kj = k % 3;
            float2 d = *(const float2*)(g_off + pid * 20 + 2 * k);
            float py  = d.x + (float)(h - 1 + ki);
            float pxf = d.y + (float)(w - 1 + kj);
            float y0f = floorf(py), x0f = floorf(pxf);
            float wy = py - y0f, wx = pxf - x0f;
            int y0 = (int)y0f, x0 = (int)x0f;
            bool vy0 = (y0 >= 0)  && (y0 <= HH - 1);
            bool vy1 = (y0 >= -1) && (y0 <= HH - 2);
            bool vx0 = (x0 >= 0)  && (x0 <= WW - 1);
            bool vx1 = (x0 >= -1) && (x0 <= WW - 2);
            float4 wv;
            wv.x = (1.f - wy) * (1.f - wx) * ((vy0 && vx0) ? 1.f : 0.f);
            wv.y = (1.f - wy) * wx         * ((vy0 && vx1) ? 1.f : 0.f);
            wv.z = wy * (1.f - wx)         * ((vy1 && vx0) ? 1.f : 0.f);
            wv.w = wy * wx                 * ((vy1 && vx1) ? 1.f : 0.f);
            int y0c = min(max(y0, 0), HH - 1), y1c = min(max(y0 + 1, 0), HH - 1);
            int x0c = min(max(x0, 0), WW - 1), x1c = min(max(x0 + 1, 0), WW - 1);
            int rowb = (pid >> 14) * HH;
            int4 iv;
            iv.x = ((rowb + y0c) * WW + x0c) * 64;
            iv.y = ((rowb + y0c) * WW + x1c) * 64;
            iv.z = ((rowb + y1c) * WW + x0c) * 64;
            iv.w = ((rowb + y1c) * WW + x1c) * 64;
            sPI[tt] = iv;
            sPF[tt] = wv;
        }
        __syncthreads();   // params visible

        ulonglong2 aA[4], aB[4];

        auto gloadTo = [&](ulonglong2* a, int k2, int pp) {
            int px = pp * 16 + sub;
            int4 iv = sPI[k2 * DCN_PX + px];
            a[0] = *(const ulonglong2*)(g_xt + iv.x + q * 4);
            a[1] = *(const ulonglong2*)(g_xt + iv.y + q * 4);
            a[2] = *(const ulonglong2*)(g_xt + iv.z + q * 4);
            a[3] = *(const ulonglong2*)(g_xt + iv.w + q * 4);
        };
        auto gstoreFrom = [&](const ulonglong2* a, int k2, int pp, float* buf) {
            int px = pp * 16 + sub;
            float4 wv = sPF[k2 * DCN_PX + px];
            unsigned long long W0 = splat2(wv.x);
            unsigned long long W1 = splat2(wv.y);
            unsigned long long W2 = splat2(wv.z);
            unsigned long long W3 = splat2(wv.w);
            unsigned long long lo = mul2(a[0].x, W0);
            lo = fma2(a[1].x, W1, lo);
            lo = fma2(a[2].x, W2, lo);
            lo = fma2(a[3].x, W3, lo);
            unsigned long long hi = mul2(a[0].y, W0);
            hi = fma2(a[1].y, W1, hi);
            hi = fma2(a[2].y, W2, hi);
            hi = fma2(a[3].y, W3, hi);
            float2 f01 = unpk2(lo);
            float2 f23 = unpk2(hi);
            int perm = (((px >> 2) ^ q) + (q >> 3)) & 15;
            float* base = buf + (4*q)*PT + 4*perm + (px & 3);
            base[0]    = f01.x;
            base[PT]   = f01.y;
            base[2*PT] = f23.x;
            base[3*PT] = f23.y;
        };

        unsigned long long acc[4][8];
        #pragma unroll
        for (int i = 0; i < 4; i++)
            #pragma unroll
            for (int j = 0; j < 8; j++) acc[i][j] = 0ULL;

        auto compute_c = [&](int c, const float* buf, const float* wcur) {
            int qc = c >> 2;
            int s  = qc >> 3;
            int permA = ((pg ^ qc) + s) & 15;
            int permB = (((pg + 8) ^ qc) + s) & 15;
            const float* row = buf + c * PT;
            ulonglong2 sA = *(const ulonglong2*)(row + 4*permA);
            ulonglong2 sB = *(const ulonglong2*)(row + 4*permB);
            const float* wp = wcur + c * 64 + obase;
            float4 wa = *(const float4*)(wp);
            float4 wb = *(const float4*)(wp + 4);
            unsigned long long w0 = splat2(wa.x);
            unsigned long long w1 = splat2(wa.y);
            unsigned long long w2 = splat2(wa.z);
            unsigned long long w3 = splat2(wa.w);
            unsigned long long w4 = splat2(wb.x);
            unsigned long long w5 = splat2(wb.y);
            unsigned long long w6 = splat2(wb.z);
            unsigned long long w7 = splat2(wb.w);
            acc[0][0] = fma2(sA.x, w0, acc[0][0]);
            acc[0][1] = fma2(sA.x, w1, acc[0][1]);
            acc[0][2] = fma2(sA.x, w2, acc[0][2]);
            acc[0][3] = fma2(sA.x, w3, acc[0][3]);
            acc[0][4] = fma2(sA.x, w4, acc[0][4]);
            acc[0][5] = fma2(sA.x, w5, acc[0][5]);
            acc[0][6] = fma2(sA.x, w6, acc[0][6]);
            acc[0][7] = fma2(sA.x, w7, acc[0][7]);
            acc[1][0] = fma2(sA.y, w0, acc[1][0]);
            acc[1][1] = fma2(sA.y, w1, acc[1][1]);
            acc[1][2] = fma2(sA.y, w2, acc[1][2]);
            acc[1][3] = fma2(sA.y, w3, acc[1][3]);
            acc[1][4] = fma2(sA.y, w4, acc[1][4]);
            acc[1][5] = fma2(sA.y, w5, acc[1][5]);
            acc[1][6] = fma2(sA.y, w6, acc[1][6]);
            acc[1][7] = fma2(sA.y, w7, acc[1][7]);
            acc[2][0] = fma2(sB.x, w0, acc[2][0]);
            acc[2][1] = fma2(sB.x, w1, acc[2][1]);
            acc[2][2] = fma2(sB.x, w2, acc[2][2]);
            acc[2][3] = fma2(sB.x, w3, acc[2][3]);
            acc[2][4] = fma2(sB.x, w4, acc[2][4]);
            acc[2][5] = fma2(sB.x, w5, acc[2][5]);
            acc[2][6] = fma2(sB.x, w6, acc[2][6]);
            acc[2][7] = fma2(sB.x, w7, acc[2][7]);
            acc[3][0] = fma2(sB.y, w0, acc[3][0]);
            acc[3][1] = fma2(sB.y, w1, acc[3][1]);
            acc[3][2] = fma2(sB.y, w2, acc[3][2]);
            acc[3][3] = fma2(sB.y, w3, acc[3][3]);
            acc[3][4] = fma2(sB.y, w4, acc[3][4]);
            acc[3][5] = fma2(sB.y, w5, acc[3][5]);
            acc[3][6] = fma2(sB.y, w6, acc[3][6]);
            acc[3][7] = fma2(sB.y, w7, acc[3][7]);
        };

        // prologue: gather tap 0 (pipelined pairwise)
        gloadTo(aA, 0, 0);
        gloadTo(aB, 0, 1);
        gstoreFrom(aA, 0, 0, sS);
        gloadTo(aA, 0, 2);
        gstoreFrom(aB, 0, 1, sS);
        gloadTo(aB, 0, 3);
        gstoreFrom(aA, 0, 2, sS);
        gstoreFrom(aB, 0, 3, sS);
        asm volatile("cp.async.wait_group 0;" ::: "memory");
        __syncthreads();

        #pragma unroll 1
        for (int k = 0; k < 9; k++) {
            const float* buf  = sS + (k & 1) * (64 * PT);
            float* nbuf       = sS + ((k + 1) & 1) * (64 * PT);
            const float* wcur = sWb + (k & 1) * 4096;
            const int c0 = 16 * ch;
            if (k < 8) {
                stage_w(k + 1, (k + 1) & 1);
                gloadTo(aA, k + 1, 0);
                gloadTo(aB, k + 1, 1);
            }
            compute_c(c0 + 0, buf, wcur);
            compute_c(c0 + 1, buf, wcur);
            compute_c(c0 + 2, buf, wcur);
            compute_c(c0 + 3, buf, wcur);
            if (k < 8) { gstoreFrom(aA, k + 1, 0, nbuf); gloadTo(aA, k + 1, 2); }
            compute_c(c0 + 4, buf, wcur);
            compute_c(c0 + 5, buf, wcur);
            compute_c(c0 + 6, buf, wcur);
            compute_c(c0 + 7, buf, wcur);
            if (k < 8) { gstoreFrom(aB, k + 1, 1, nbuf); gloadTo(aB, k + 1, 3); }
            compute_c(c0 + 8, buf, wcur);
            compute_c(c0 + 9, buf, wcur);
            compute_c(c0 + 10, buf, wcur);
            compute_c(c0 + 11, buf, wcur);
            if (k < 8) gstoreFrom(aA, k + 1, 2, nbuf);
            compute_c(c0 + 12, buf, wcur);
            compute_c(c0 + 13, buf, wcur);
            compute_c(c0 + 14, buf, wcur);
            compute_c(c0 + 15, buf, wcur);
            if (k < 8) gstoreFrom(aB, k + 1, 3, nbuf);
            asm volatile("cp.async.wait_group 0;" ::: "memory");
            __syncthreads();
        }

        // ---- cross-warp c-split reduction (4 -> 1) through smem ----
        float* RA = sRed;              // 4096 floats (16KB)
        float* RB = sRed + 4096;       // 4096 floats

        auto store_acc = [&](float* R) {
            #pragma unroll
            for (int i = 0; i < 16; i++) {
                int pi = i >> 2, j2 = (i & 3) * 2;
                ulonglong2 v;
                v.x = acc[pi][j2];
                v.y = acc[pi][j2 + 1];
                *(ulonglong2*)(R + Q*2048 + i*128 + lane*4) = v;
            }
        };
        auto load_add = [&](const float* R) {
            #pragma unroll
            for (int i = 0; i < 16; i++) {
                int pi = i >> 2, j2 = (i & 3) * 2;
                ulonglong2 v = *(const ulonglong2*)(R + Q*2048 + i*128 + lane*4);
                acc[pi][j2]     = add2(acc[pi][j2], v.x);
                acc[pi][j2 + 1] = add2(acc[pi][j2 + 1], v.y);
            }
        };

        if (ch == 1) store_acc(RA);
        if (ch == 3) store_acc(RB);
        __syncthreads();
        if (ch == 0) load_add(RA);
        if (ch == 2) load_add(RB);
        __syncthreads();
        if (ch == 2) store_acc(RA);
        __syncthreads();
        if (ch == 0) load_add(RA);

        // ---- epilogue: warps 0,1 hold full sums; write NCHW + BN partials --
        if (wid < 2) {
            int b = pixbase >> 14;
            int rem0 = pixbase & (HWW - 1);
            #pragma unroll
            for (int pi = 0; pi < 4; pi++) {
                int pxl = 4*pg + (pi & 1)*2 + (pi >> 1)*32;
                #pragma unroll
                for (int j = 0; j < 8; j++) {
                    int o = obase + j;
                    float2 f = unpk2(acc[pi][j]);
                    *(float2*)(out + (b*64 + o)*HWW + rem0 + pxl) = f;
                    sBN[tid*17 + j]     += f.x + f.y;
                    sBN[tid*17 + 8 + j] += f.x*f.x + f.y*f.y;
                }
            }
        }
    }

    // ---- final BN partials: pull from smem, reduce over pg lanes ----
    if (wid < 2) {
        float bsum[8], bsq[8];
        #pragma unroll
        for (int j = 0; j < 8; j++) {
            bsum[j] = sBN[tid*17 + j];
            bsq[j]  = sBN[tid*17 + 8 + j];
        }
        #pragma unroll
        for (int j = 0; j < 8; j++) {
            #pragma unroll
            for (int d = 1; d < 8; d <<= 1) {
                bsum[j] += __shfl_xor_sync(0xffffffffu, bsum[j], d);
                bsq[j]  += __shfl_xor_sync(0xffffffffu, bsq[j],  d);
            }
        }
        if (pg == 0) {
            #pragma unroll
            for (int j = 0; j < 8; j++)
                g_part[blockIdx.x * 64 + obase + j] = make_float2(bsum[j], bsq[j]);
        }
    }
}

// ---------------------------------------------------------------------------
// Kernel 3: finalize mean / istd — parallel: one block per channel.
// ---------------------------------------------------------------------------
__global__ __launch_bounds__(128) void k_bnfin() {
    int o = blockIdx.x;                    // channel
    int tid = threadIdx.x;
    float s = 0.f, q = 0.f;
    for (int j = tid; j < DCN_GRID; j += 128) {
        float2 p = g_part[j * 64 + o];
        s += p.x; q += p.y;
    }
    #pragma unroll
    for (int d = 16; d; d >>= 1) {
        s += __shfl_xor_sync(0xffffffffu, s, d);
        q += __shfl_xor_sync(0xffffffffu, q, d);
    }
    __shared__ float2 red[4];
    if ((tid & 31) == 0) red[tid >> 5] = make_float2(s, q);
    __syncthreads();
    if (tid == 0) {
        float ts = 0.f, tq = 0.f;
        #pragma unroll
        for (int i = 0; i < 4; i++) { ts += red[i].x; tq += red[i].y; }
        float inv_n = 1.f / (float)(BB * HWW);
        float mean = ts * inv_n;
        float var  = tq * inv_n - mean * mean;
        g_mean[o] = mean;
        g_istd[o] = rsqrtf(var + 1e-5f);
    }
}

// ---------------------------------------------------------------------------
// Kernel 4: normalize + affine + ReLU
// ---------------------------------------------------------------------------
__global__ __launch_bounds__(256) void k_bnapply(float* __restrict__ out,
                                                 const float* __restrict__ gamma,
                                                 const float* __restrict__ beta) {
    int i4 = blockIdx.x * 256 + threadIdx.x;
    int i = i4 * 4;
    int o = (i / HWW) % 64;
    float scale = g_istd[o] * __ldg(gamma + o);
    float shift = __ldg(beta + o) - g_mean[o] * scale;
    float4 v = *((float4*)out + i4);
    v.x = fmaxf(v.x * scale + shift, 0.f);
    v.y = fmaxf(v.y * scale + shift, 0.f);
    v.z = fmaxf(v.z * scale + shift, 0.f);
    v.w = fmaxf(v.w * scale + shift, 0.f);
    *((float4*)out + i4) = v;
}

// ---------------------------------------------------------------------------
extern "C" void kernel_launch(void* const* d_in, const int* in_sizes, int n_in,
                              void* d_out, int out_size) {
    const float* x     = (const float*)d_in[0];
    const float* ow    = (const float*)d_in[1];
    const float* ob    = (const float*)d_in[2];
    const float* dw    = (const float*)d_in[3];
    const float* gamma = (const float*)d_in[4];
    const float* beta  = (const float*)d_in[5];
    float* out = (float*)d_out;

    k_prep<<<(9*64*64 + 9*64*20 + 255) / 256, 256>>>(dw, ow);

    const int off_smem = (11520 + 8192) * 4;      // 78848
    cudaFuncSetAttribute(k_offconv, cudaFuncAttributeMaxDynamicSharedMemorySize, off_smem);
    k_offconv<<<BB * (HH / 2), 256, off_smem>>>(x, ob);

    const int dcn_smem = 90384;
    cudaFuncSetAttribute(k_dcn, cudaFuncAttributeMaxDynamicSharedMemorySize, dcn_smem);
    k_dcn<<<DCN_GRID, 256, dcn_smem>>>(out);

    k_bnfin<<<64, 128>>>();

    k_bnapply<<<(BB * 64 * HWW / 4) / 256, 256>>>(out, gamma, beta);
}

// round 13
// speedup vs baseline: 1.0391x; 1.0391x over previous
#include <cuda_runtime.h>
#include <cuda_bf16.h>

#define BB 4
#define CC 64
#define HH 128
#define WW 128
#define HWW (HH*WW)
#define NPIX (BB*HH*WW)

#define DCN_PX 64
#define PT 68                      // sample-buffer row pitch (floats)
#define NTILES (NPIX/DCN_PX)       // 1024
#define DCN_GRID 296

// Scratch (allocation-free rule: device globals)
__device__ float g_xt[BB*HH*WW*CC];       // NHWC input (for dcn gathers)
__device__ float g_off[NPIX*20];          // offsets, pitch 20
__device__ float g_wt[9*64*64];           // dcn weights [k][c][o]
__device__ float g_owt[9*64*20];          // offset-conv weights [k][c][20]
__device__ float2 g_part[DCN_GRID*64];    // fused bnstats partials

// ---------------- packed f32x2 helpers ----------------
__device__ __forceinline__ unsigned long long splat2(float x) {
    unsigned long long r;
    asm("mov.b64 %0, {%1, %1};" : "=l"(r) : "f"(x));
    return r;
}
__device__ __forceinline__ unsigned long long pack2(float x, float y) {
    unsigned long long r;
    asm("mov.b64 %0, {%1, %2};" : "=l"(r) : "f"(x), "f"(y));
    return r;
}
__device__ __forceinline__ unsigned long long fma2(unsigned long long a,
                                                   unsigned long long b,
                                                   unsigned long long c) {
    unsigned long long d;
    asm("fma.rn.f32x2 %0, %1, %2, %3;" : "=l"(d) : "l"(a), "l"(b), "l"(c));
    return d;
}
__device__ __forceinline__ unsigned long long mul2(unsigned long long a,
                                                   unsigned long long b) {
    unsigned long long d;
    asm("mul.rn.f32x2 %0, %1, %2;" : "=l"(d) : "l"(a), "l"(b));
    return d;
}
__device__ __forceinline__ unsigned long long add2(unsigned long long a,
                                                   unsigned long long b) {
    unsigned long long d;
    asm("add.rn.f32x2 %0, %1, %2;" : "=l"(d) : "l"(a), "l"(b));
    return d;
}
__device__ __forceinline__ float2 unpk2(unsigned long long v) {
    float2 f;
    asm("mov.b64 {%0, %1}, %2;" : "=f"(f.x), "=f"(f.y) : "l"(v));
    return f;
}

// ---------------------------------------------------------------------------
// Kernel P: one-time weight transposes.
// ---------------------------------------------------------------------------
__global__ void k_prep(const float* __restrict__ dw, const float* __restrict__ ow) {
    int idx = blockIdx.x * 256 + threadIdx.x;
    if (idx < 9*64*64) {
        int k = idx / 4096;
        int r = idx % 4096;
        int c = r / 64;
        int o = r % 64;
        g_wt[idx] = dw[(o*64 + c)*9 + k];
    } else {
        int j = idx - 9*64*64;
        if (j < 9*64*20) {
            int k = j / 1280;
            int r = j % 1280;
            int c = r / 20;
            int o = r % 20;
            g_owt[j] = (o < 18) ? ow[(o*64 + c)*9 + k] : 0.f;
        }
    }
}

// ---------------------------------------------------------------------------
// Kernel 1: offset conv 3x3, 64 -> 18ch. Reads NCHW x (coalesced).
// ALSO emits the NHWC transpose g_xt for its own 2 rows (from staged tiles).
// ---------------------------------------------------------------------------
__global__ __launch_bounds__(256) void k_offconv(const float* __restrict__ x,
                                                 const float* __restrict__ ob) {
    extern __shared__ float sm[];
    float* sOW = sm;                 // 11520 floats
    float* xt  = sm + 11520;         // 8192 floats

    int tid = threadIdx.x;
    for (int i4 = tid; i4 < 2880; i4 += 256)
        ((float4*)sOW)[i4] = ((const float4*)g_owt)[i4];

    int b  = blockIdx.x >> 6;
    int y0 = (blockIdx.x & 63) * 2;
    int py = tid >> 7;               // 0..1
    int w  = tid & 127;
    int pid = b * HWW + (y0 + py) * WW + w;

    unsigned long long acc[9];
    #pragma unroll
    for (int j = 0; j < 9; j++) acc[j] = pack2(__ldg(ob + 2*j), __ldg(ob + 2*j + 1));

    #pragma unroll 1
    for (int cc = 0; cc < 4; cc++) {
        __syncthreads();
        #pragma unroll
        for (int j = 0; j < 8; j++) {
            int i4 = tid + j * 256;
            int ci = i4 >> 7;
            int r  = (i4 >> 5) & 3;
            int w4 = i4 & 31;
            int yr = y0 - 1 + r;
            float4 v = make_float4(0.f, 0.f, 0.f, 0.f);
            if (yr >= 0 && yr < HH)
                v = *((const float4*)(x + ((b*64 + cc*16 + ci)*HH + yr)*WW) + w4);
            ((float4*)xt)[i4] = v;
        }
        __syncthreads();

        #pragma unroll
        for (int ki = 0; ki < 3; ki++) {
            int r = py + ki;
            #pragma unroll
            for (int kj = 0; kj < 3; kj++) {
                int xx = w - 1 + kj;
                if (xx < 0 || xx >= WW) continue;
                const float* wk0 = sOW + ((ki*3 + kj)*64 + cc*16) * 20;
                const float* xr = xt + r*128 + xx;
                #pragma unroll 4
                for (int ci = 0; ci < 16; ci++) {
                    unsigned long long s2 = splat2(xr[ci * 512]);
                    const float* wr = wk0 + ci * 20;
                    const ulonglong2* w2 = (const ulonglong2*)wr;
                    ulonglong2 wa = w2[0];
                    ulonglong2 wb = w2[1];
                    unsigned long long wc = *(const unsigned long long*)(wr + 16);
                    acc[0] = fma2(s2, wa.x, acc[0]);
                    acc[1] = fma2(s2, wa.y, acc[1]);
                    acc[2] = fma2(s2, wb.x, acc[2]);
                    acc[3] = fma2(s2, wb.y, acc[3]);
                    acc[8] = fma2(s2, wc,   acc[8]);
                    const ulonglong2* w3 = (const ulonglong2*)(wr + 8);
                    ulonglong2 wd = w3[0];
                    ulonglong2 we = w3[1];
                    acc[4] = fma2(s2, wd.x, acc[4]);
                    acc[5] = fma2(s2, wd.y, acc[5]);
                    acc[6] = fma2(s2, we.x, acc[6]);
                    acc[7] = fma2(s2, we.y, acc[7]);
                }
            }
        }

        // ---- NHWC transpose emit for this pixel's 16 channels of chunk cc ----
        {
            const float* xc = xt + (py + 1) * 128 + w;   // center row = y0+py
            float4 o0 = make_float4(xc[0*512], xc[1*512], xc[2*512],  xc[3*512]);
            float4 o1 = make_float4(xc[4*512], xc[5*512], xc[6*512],  xc[7*512]);
            float4 o2 = make_float4(xc[8*512], xc[9*512], xc[10*512], xc[11*512]);
            float4 o3 = make_float4(xc[12*512],xc[13*512],xc[14*512], xc[15*512]);
            float4* dst = (float4*)(g_xt + (size_t)pid * 64 + cc * 16);
            dst[0] = o0; dst[1] = o1; dst[2] = o2; dst[3] = o3;
        }
    }
    float2* op = (float2*)(g_off + pid * 20);
    #pragma unroll
    for (int j = 0; j < 9; j++) op[j] = unpk2(acc[j]);
}

// ---------------------------------------------------------------------------
// Kernel 2: deformable sampling + DCN conv.  (exact R9 best-known version)
// ---------------------------------------------------------------------------
__global__ __launch_bounds__(256, 2) void k_dcn(float* __restrict__ out) {
    extern __shared__ char smem[];
    float*  sS  = (float*)smem;                     // [2][64][PT]
    float*  sWb = (float*)(smem + 34816);           // [2][4096]
    float*  sRed = (float*)(smem + 34816);          // reduce region (reuses sWb)
    int4*   sPI = (int4*)(smem + 67584);            // [9*64]
    float4* sPF = (float4*)(smem + 76800);          // [9*64]

    const int tid = threadIdx.x;
    // gather mapping
    const int q   = tid & 15;          // channel chunk (4 c's)
    const int sub = tid >> 4;          // pixel-within-pass
    // compute mapping
    const int lane = tid & 31;
    const int wid  = tid >> 5;
    const int Q    = wid & 1;          // o half
    const int ch   = wid >> 1;         // c quarter (16 c's)
    const int pg   = lane & 7;         // pixel quad
    const int osub = (lane >> 3) & 3;
    const int obase = 32*Q + 8*osub;   // 8 o's per thread

    auto stage_w = [&](int k, int buf) {
        const float* src = g_wt + k * 4096 + tid * 4;
        unsigned dst = (unsigned)__cvta_generic_to_shared(sWb + buf * 4096 + tid * 4);
        #pragma unroll
        for (int j = 0; j < 4; j++) {
            asm volatile("cp.async.cg.shared.global [%0], [%1], 16;"
                         :: "r"(dst + j * 4096), "l"(src + j * 1024) : "memory");
        }
        asm volatile("cp.async.commit_group;" ::: "memory");
    };

    float bsum[8], bsq[8];
    #pragma unroll
    for (int j = 0; j < 8; j++) { bsum[j] = 0.f; bsq[j] = 0.f; }

    for (int t = blockIdx.x; t < NTILES; t += DCN_GRID) {
        const int pixbase = t * DCN_PX;

        __syncthreads();   // previous tile's reduce/writes done
        stage_w(0, 0);     // overlap with params computation below

        // ---- sampling params for all (k, px) ----
        for (int tt = tid; tt < 9 * DCN_PX; tt += 256) {
            int k  = tt / DCN_PX;
            int px = tt % DCN_PX;
            int pid = pixbase + px;
            int rem = pid & (HWW - 1);
            int h   = rem / WW;
            int w   = rem % WW;
            int ki = k / 3, kj = k % 3;
            float2 d = *(const float2*)(g_off + pid * 20 + 2 * k);
            float py  = d.x + (float)(h - 1 + ki);
            float pxf = d.y + (float)(w - 1 + kj);
            float y0f = floorf(py), x0f = floorf(pxf);
            float wy = py - y0f, wx = pxf - x0f;
            int y0 = (int)y0f, x0 = (int)x0f;
            bool vy0 = (y0 >= 0)  && (y0 <= HH - 1);
            bool vy1 = (y0 >= -1) && (y0 <= HH - 2);
            bool vx0 = (x0 >= 0)  && (x0 <= WW - 1);
            bool vx1 = (x0 >= -1) && (x0 <= WW - 2);
            float4 wv;
            wv.x = (1.f - wy) * (1.f - wx) * ((vy0 && vx0) ? 1.f : 0.f);
            wv.y = (1.f - wy) * wx         * ((vy0 && vx1) ? 1.f : 0.f);
            wv.z = wy * (1.f - wx)         * ((vy1 && vx0) ? 1.f : 0.f);
            wv.w = wy * wx                 * ((vy1 && vx1) ? 1.f : 0.f);
            int y0c = min(max(y0, 0), HH - 1), y1c = min(max(y0 + 1, 0), HH - 1);
            int x0c = min(max(x0, 0), WW - 1), x1c = min(max(x0 + 1, 0), WW - 1);
            int rowb = (pid >> 14) * HH;
            int4 iv;
            iv.x = ((rowb + y0c) * WW + x0c) * 64;
            iv.y = ((rowb + y0c) * WW + x1c) * 64;
            iv.z = ((rowb + y1c) * WW + x0c) * 64;
            iv.w = ((rowb + y1c) * WW + x1c) * 64;
            sPI[tt] = iv;
            sPF[tt] = wv;
        }
        __syncthreads();   // params visible

        ulonglong2 a[4];
        float4 wvf;

        auto gload = [&](int k, int pp) {
            int px = pp * 16 + sub;
            int4 iv = sPI[k * DCN_PX + px];
            wvf = sPF[k * DCN_PX + px];
            a[0] = *(const ulonglong2*)(g_xt + iv.x + q * 4);
            a[1] = *(const ulonglong2*)(g_xt + iv.y + q * 4);
            a[2] = *(const ulonglong2*)(g_xt + iv.z + q * 4);
            a[3] = *(const ulonglong2*)(g_xt + iv.w + q * 4);
        };
        auto gstore = [&](int pp, float* buf) {
            int px = pp * 16 + sub;
            unsigned long long W0 = splat2(wvf.x);
            unsigned long long W1 = splat2(wvf.y);
            unsigned long long W2 = splat2(wvf.z);
            unsigned long long W3 = splat2(wvf.w);
            unsigned long long lo = mul2(a[0].x, W0);
            lo = fma2(a[1].x, W1, lo);
            lo = fma2(a[2].x, W2, lo);
            lo = fma2(a[3].x, W3, lo);
            unsigned long long hi = mul2(a[0].y, W0);
            hi = fma2(a[1].y, W1, hi);
            hi = fma2(a[2].y, W2, hi);
            hi = fma2(a[3].y, W3, hi);
            float2 f01 = unpk2(lo);
            float2 f23 = unpk2(hi);
            int perm = (((px >> 2) ^ q) + (q >> 3)) & 15;
            float* base = buf + (4*q)*PT + 4*perm + (px & 3);
            base[0]    = f01.x;
            base[PT]   = f01.y;
            base[2*PT] = f23.x;
            base[3*PT] = f23.y;
        };

        unsigned long long acc[4][8];
        #pragma unroll
        for (int i = 0; i < 4; i++)
            #pragma unroll
            for (int j = 0; j < 8; j++) acc[i][j] = 0ULL;

        auto compute_c = [&](int c, const float* buf, const float* wcur) {
            int qc = c >> 2;
            int s  = qc >> 3;
            int permA = ((pg ^ qc) + s) & 15;
            int permB = (((pg + 8) ^ qc) + s) & 15;
            const float* row = buf + c * PT;
            ulonglong2 sA = *(const ulonglong2*)(row + 4*permA);
            ulonglong2 sB = *(const ulonglong2*)(row + 4*permB);
            const float* wp = wcur + c * 64 + obase;
            float4 wa = *(const float4*)(wp);
            float4 wb = *(const float4*)(wp + 4);
            unsigned long long w0 = splat2(wa.x);
            unsigned long long w1 = splat2(wa.y);
            unsigned long long w2 = splat2(wa.z);
            unsigned long long w3 = splat2(wa.w);
            unsigned long long w4 = splat2(wb.x);
            unsigned long long w5 = splat2(wb.y);
            unsigned long long w6 = splat2(wb.z);
            unsigned long long w7 = splat2(wb.w);
            acc[0][0] = fma2(sA.x, w0, acc[0][0]);
            acc[0][1] = fma2(sA.x, w1, acc[0][1]);
            acc[0][2] = fma2(sA.x, w2, acc[0][2]);
            acc[0][3] = fma2(sA.x, w3, acc[0][3]);
            acc[0][4] = fma2(sA.x, w4, acc[0][4]);
            acc[0][5] = fma2(sA.x, w5, acc[0][5]);
            acc[0][6] = fma2(sA.x, w6, acc[0][6]);
            acc[0][7] = fma2(sA.x, w7, acc[0][7]);
            acc[1][0] = fma2(sA.y, w0, acc[1][0]);
            acc[1][1] = fma2(sA.y, w1, acc[1][1]);
            acc[1][2] = fma2(sA.y, w2, acc[1][2]);
            acc[1][3] = fma2(sA.y, w3, acc[1][3]);
            acc[1][4] = fma2(sA.y, w4, acc[1][4]);
            acc[1][5] = fma2(sA.y, w5, acc[1][5]);
            acc[1][6] = fma2(sA.y, w6, acc[1][6]);
            acc[1][7] = fma2(sA.y, w7, acc[1][7]);
            acc[2][0] = fma2(sB.x, w0, acc[2][0]);
            acc[2][1] = fma2(sB.x, w1, acc[2][1]);
            acc[2][2] = fma2(sB.x, w2, acc[2][2]);
            acc[2][3] = fma2(sB.x, w3, acc[2][3]);
            acc[2][4] = fma2(sB.x, w4, acc[2][4]);
            acc[2][5] = fma2(sB.x, w5, acc[2][5]);
            acc[2][6] = fma2(sB.x, w6, acc[2][6]);
            acc[2][7] = fma2(sB.x, w7, acc[2][7]);
            acc[3][0] = fma2(sB.y, w0, acc[3][0]);
            acc[3][1] = fma2(sB.y, w1, acc[3][1]);
            acc[3][2] = fma2(sB.y, w2, acc[3][2]);
            acc[3][3] = fma2(sB.y, w3, acc[3][3]);
            acc[3][4] = fma2(sB.y, w4, acc[3][4]);
            acc[3][5] = fma2(sB.y, w5, acc[3][5]);
            acc[3][6] = fma2(sB.y, w6, acc[3][6]);
            acc[3][7] = fma2(sB.y, w7, acc[3][7]);
        };

        // prologue: gather tap 0
        #pragma unroll
        for (int pp = 0; pp < 4; pp++) {
            gload(0, pp);
            gstore(pp, sS);
        }
        asm volatile("cp.async.wait_group 0;" ::: "memory");
        __syncthreads();

        #pragma unroll 1
        for (int k = 0; k < 9; k++) {
            const float* buf  = sS + (k & 1) * (64 * PT);
            float* nbuf       = sS + ((k + 1) & 1) * (64 * PT);
            const float* wcur = sWb + (k & 1) * 4096;
            if (k < 8) stage_w(k + 1, (k + 1) & 1);
            #pragma unroll
            for (int pp = 0; pp < 4; pp++) {
                if (k < 8) gload(k + 1, pp);
                int c0 = 16 * ch + 4 * pp;
                compute_c(c0 + 0, buf, wcur);
                compute_c(c0 + 1, buf, wcur);
                compute_c(c0 + 2, buf, wcur);
                compute_c(c0 + 3, buf, wcur);
                if (k < 8) gstore(pp, nbuf);
            }
            asm volatile("cp.async.wait_group 0;" ::: "memory");
            __syncthreads();
        }

        // ---- cross-warp c-split reduction (4 -> 1) through smem ----
        float* RA = sRed;              // 4096 floats (16KB)
        float* RB = sRed + 4096;       // 4096 floats

        auto store_acc = [&](float* R) {
            #pragma unroll
            for (int i = 0; i < 16; i++) {
                int pi = i >> 2, j2 = (i & 3) * 2;
                ulonglong2 v;
                v.x = acc[pi][j2];
                v.y = acc[pi][j2 + 1];
                *(ulonglong2*)(R + Q*2048 + i*128 + lane*4) = v;
            }
        };
        auto load_add = [&](const float* R) {
            #pragma unroll
            for (int i = 0; i < 16; i++) {
                int pi = i >> 2, j2 = (i & 3) * 2;
                ulonglong2 v = *(const ulonglong2*)(R + Q*2048 + i*128 + lane*4);
                acc[pi][j2]     = add2(acc[pi][j2], v.x);
                acc[pi][j2 + 1] = add2(acc[pi][j2 + 1], v.y);
            }
        };

        if (ch == 1) store_acc(RA);
        if (ch == 3) store_acc(RB);
        __syncthreads();
        if (ch == 0) load_add(RA);
        if (ch == 2) load_add(RB);
        __syncthreads();
        if (ch == 2) store_acc(RA);
        __syncthreads();
        if (ch == 0) load_add(RA);

        // ---- epilogue: warps 0,1 hold full sums; write NCHW + BN partials --
        if (wid < 2) {
            int b = pixbase >> 14;
            int rem0 = pixbase & (HWW - 1);
            #pragma unroll
            for (int pi = 0; pi < 4; pi++) {
                int pxl = 4*pg + (pi & 1)*2 + (pi >> 1)*32;
                #pragma unroll
                for (int j = 0; j < 8; j++) {
                    int o = obase + j;
                    float2 f = unpk2(acc[pi][j]);
                    *(float2*)(out + (b*64 + o)*HWW + rem0 + pxl) = f;
                    bsum[j] += f.x + f.y;
                    bsq[j]  += f.x*f.x + f.y*f.y;
                }
            }
        }
    }

    // ---- final BN partials: reduce over pg lanes, write per-block ----
    if (wid < 2) {
        #pragma unroll
        for (int j = 0; j < 8; j++) {
            #pragma unroll
            for (int d = 1; d < 8; d <<= 1) {
                bsum[j] += __shfl_xor_sync(0xffffffffu, bsum[j], d);
                bsq[j]  += __shfl_xor_sync(0xffffffffu, bsq[j],  d);
            }
        }
        if (pg == 0) {
            #pragma unroll
            for (int j = 0; j < 8; j++)
                g_part[blockIdx.x * 64 + obase + j] = make_float2(bsum[j], bsq[j]);
        }
    }
}

// ---------------------------------------------------------------------------
// Kernel 3: fused BN finalize + normalize + affine + ReLU.
// 1024 blocks; each covers a quarter-channel (o constant per block).
// Block first reduces the 296 per-block partials for its channel, then applies.
// ---------------------------------------------------------------------------
__global__ __launch_bounds__(256) void k_bnapply(float* __restrict__ out,
                                                 const float* __restrict__ gamma,
                                                 const float* __restrict__ beta) {
    const int tid = threadIdx.x;
    const int o = (blockIdx.x >> 2) & 63;

    // reduce this channel's partials (296 entries)
    float s = 0.f, qq = 0.f;
    for (int j = tid; j < DCN_GRID; j += 256) {
        float2 p = g_part[j * 64 + o];
        s += p.x; qq += p.y;
    }
    #pragma unroll
    for (int d = 16; d; d >>= 1) {
        s  += __shfl_xor_sync(0xffffffffu, s,  d);
        qq += __shfl_xor_sync(0xffffffffu, qq, d);
    }
    __shared__ float2 red[8];
    __shared__ float2 bc;
    if ((tid & 31) == 0) red[tid >> 5] = make_float2(s, qq);
    __syncthreads();
    if (tid == 0) {
        float ts = 0.f, tq = 0.f;
        #pragma unroll
        for (int i = 0; i < 8; i++) { ts += red[i].x; tq += red[i].y; }
        float inv_n = 1.f / (float)(BB * HWW);
        float mean = ts * inv_n;
        float var  = tq * inv_n - mean * mean;
        float istd = rsqrtf(var + 1e-5f);
        float scale = istd * __ldg(gamma + o);
        float shift = __ldg(beta + o) - mean * scale;
        bc = make_float2(scale, shift);
    }
    __syncthreads();
    const float scale = bc.x;
    const float shift = bc.y;

    // apply to this block's quarter-channel: 1024 float4, 4 per thread
    int base4 = blockIdx.x * 1024 + tid;
    #pragma unroll
    for (int j = 0; j < 4; j++) {
        int i4 = base4 + j * 256;
        float4 v = *((float4*)out + i4);
        v.x = fmaxf(v.x * scale + shift, 0.f);
        v.y = fmaxf(v.y * scale + shift, 0.f);
        v.z = fmaxf(v.z * scale + shift, 0.f);
        v.w = fmaxf(v.w * scale + shift, 0.f);
        *((float4*)out + i4) = v;
    }
}

// ---------------------------------------------------------------------------
extern "C" void kernel_launch(void* const* d_in, const int* in_sizes, int n_in,
                              void* d_out, int out_size) {
    const float* x     = (const float*)d_in[0];
    const float* ow    = (const float*)d_in[1];
    const float* ob    = (const float*)d_in[2];
    const float* dw    = (const float*)d_in[3];
    const float* gamma = (const float*)d_in[4];
    const float* beta  = (const float*)d_in[5];
    float* out = (float*)d_out;

    k_prep<<<(9*64*64 + 9*64*20 + 255) / 256, 256>>>(dw, ow);

    const int off_smem = (11520 + 8192) * 4;      // 78848
    cudaFuncSetAttribute(k_offconv, cudaFuncAttributeMaxDynamicSharedMemorySize, off_smem);
    k_offconv<<<BB * (HH / 2), 256, off_smem>>>(x, ob);

    const int dcn_smem = 86016;
    cudaFuncSetAttribute(k_dcn, cudaFuncAttributeMaxDynamicSharedMemorySize, dcn_smem);
    k_dcn<<<DCN_GRID, 256, dcn_smem>>>(out);

    k_bnapply<<<1024, 256>>>(out, gamma, beta);
}

// round 14
// speedup vs baseline: 1.0425x; 1.0033x over previous
#include <cuda_runtime.h>
#include <cuda_bf16.h>

#define BB 4
#define CC 64
#define HH 128
#define WW 128
#define HWW (HH*WW)
#define NPIX (BB*HH*WW)

#define DCN_PX 64
#define PT 68                      // sample-buffer row pitch (floats)
#define NTILES (NPIX/DCN_PX)       // 1024
#define DCN_GRID 296

// Scratch (allocation-free rule: device globals)
__device__ float g_xt[BB*HH*WW*CC];       // NHWC input (for dcn gathers)
__device__ float g_off[NPIX*20];          // offsets, pitch 20
__device__ float g_wt[9*64*64];           // dcn weights [k][c][o]
__device__ float g_owt[9*64*20];          // offset-conv weights [k][c][20]
__device__ float2 g_part[DCN_GRID*64];    // fused bnstats partials

// ---------------- packed f32x2 helpers ----------------
__device__ __forceinline__ unsigned long long splat2(float x) {
    unsigned long long r;
    asm("mov.b64 %0, {%1, %1};" : "=l"(r) : "f"(x));
    return r;
}
__device__ __forceinline__ unsigned long long pack2(float x, float y) {
    unsigned long long r;
    asm("mov.b64 %0, {%1, %2};" : "=l"(r) : "f"(x), "f"(y));
    return r;
}
__device__ __forceinline__ unsigned long long fma2(unsigned long long a,
                                                   unsigned long long b,
                                                   unsigned long long c) {
    unsigned long long d;
    asm("fma.rn.f32x2 %0, %1, %2, %3;" : "=l"(d) : "l"(a), "l"(b), "l"(c));
    return d;
}
__device__ __forceinline__ unsigned long long mul2(unsigned long long a,
                                                   unsigned long long b) {
    unsigned long long d;
    asm("mul.rn.f32x2 %0, %1, %2;" : "=l"(d) : "l"(a), "l"(b));
    return d;
}
__device__ __forceinline__ unsigned long long add2(unsigned long long a,
                                                   unsigned long long b) {
    unsigned long long d;
    asm("add.rn.f32x2 %0, %1, %2;" : "=l"(d) : "l"(a), "l"(b));
    return d;
}
__device__ __forceinline__ float2 unpk2(unsigned long long v) {
    float2 f;
    asm("mov.b64 {%0, %1}, %2;" : "=f"(f.x), "=f"(f.y) : "l"(v));
    return f;
}

// ---------------------------------------------------------------------------
// Kernel P: one-time weight transposes.
// ---------------------------------------------------------------------------
__global__ void k_prep(const float* __restrict__ dw, const float* __restrict__ ow) {
    int idx = blockIdx.x * 256 + threadIdx.x;
    if (idx < 9*64*64) {
        int k = idx / 4096;
        int r = idx % 4096;
        int c = r / 64;
        int o = r % 64;
        g_wt[idx] = dw[(o*64 + c)*9 + k];
    } else {
        int j = idx - 9*64*64;
        if (j < 9*64*20) {
            int k = j / 1280;
            int r = j % 1280;
            int c = r / 20;
            int o = r % 20;
            g_owt[j] = (o < 18) ? ow[(o*64 + c)*9 + k] : 0.f;
        }
    }
}

// ---------------------------------------------------------------------------
// Kernel 1: offset conv 3x3, 64 -> 18ch. Reads NCHW x (coalesced).
// ALSO emits the NHWC transpose g_xt for its own 2 rows (from staged tiles).
// ---------------------------------------------------------------------------
__global__ __launch_bounds__(256) void k_offconv(const float* __restrict__ x,
                                                 const float* __restrict__ ob) {
    extern __shared__ float sm[];
    float* sOW = sm;                 // 11520 floats
    float* xt  = sm + 11520;         // 8192 floats

    int tid = threadIdx.x;
    for (int i4 = tid; i4 < 2880; i4 += 256)
        ((float4*)sOW)[i4] = ((const float4*)g_owt)[i4];

    int b  = blockIdx.x >> 6;
    int y0 = (blockIdx.x & 63) * 2;
    int py = tid >> 7;               // 0..1
    int w  = tid & 127;
    int pid = b * HWW + (y0 + py) * WW + w;

    unsigned long long acc[9];
    #pragma unroll
    for (int j = 0; j < 9; j++) acc[j] = pack2(__ldg(ob + 2*j), __ldg(ob + 2*j + 1));

    #pragma unroll 1
    for (int cc = 0; cc < 4; cc++) {
        __syncthreads();
        #pragma unroll
        for (int j = 0; j < 8; j++) {
            int i4 = tid + j * 256;
            int ci = i4 >> 7;
            int r  = (i4 >> 5) & 3;
            int w4 = i4 & 31;
            int yr = y0 - 1 + r;
            float4 v = make_float4(0.f, 0.f, 0.f, 0.f);
            if (yr >= 0 && yr < HH)
                v = *((const float4*)(x + ((b*64 + cc*16 + ci)*HH + yr)*WW) + w4);
            ((float4*)xt)[i4] = v;
        }
        __syncthreads();

        #pragma unroll
        for (int ki = 0; ki < 3; ki++) {
            int r = py + ki;
            #pragma unroll
            for (int kj = 0; kj < 3; kj++) {
                int xx = w - 1 + kj;
                if (xx < 0 || xx >= WW) continue;
                const float* wk0 = sOW + ((ki*3 + kj)*64 + cc*16) * 20;
                const float* xr = xt + r*128 + xx;
                #pragma unroll 4
                for (int ci = 0; ci < 16; ci++) {
                    unsigned long long s2 = splat2(xr[ci * 512]);
                    const float* wr = wk0 + ci * 20;
                    const ulonglong2* w2 = (const ulonglong2*)wr;
                    ulonglong2 wa = w2[0];
                    ulonglong2 wb = w2[1];
                    unsigned long long wc = *(const unsigned long long*)(wr + 16);
                    acc[0] = fma2(s2, wa.x, acc[0]);
                    acc[1] = fma2(s2, wa.y, acc[1]);
                    acc[2] = fma2(s2, wb.x, acc[2]);
                    acc[3] = fma2(s2, wb.y, acc[3]);
                    acc[8] = fma2(s2, wc,   acc[8]);
                    const ulonglong2* w3 = (const ulonglong2*)(wr + 8);
                    ulonglong2 wd = w3[0];
                    ulonglong2 we = w3[1];
                    acc[4] = fma2(s2, wd.x, acc[4]);
                    acc[5] = fma2(s2, wd.y, acc[5]);
                    acc[6] = fma2(s2, we.x, acc[6]);
                    acc[7] = fma2(s2, we.y, acc[7]);
                }
            }
        }

        // ---- NHWC transpose emit for this pixel's 16 channels of chunk cc ----
        {
            const float* xc = xt + (py + 1) * 128 + w;   // center row = y0+py
            float4 o0 = make_float4(xc[0*512], xc[1*512], xc[2*512],  xc[3*512]);
            float4 o1 = make_float4(xc[4*512], xc[5*512], xc[6*512],  xc[7*512]);
            float4 o2 = make_float4(xc[8*512], xc[9*512], xc[10*512], xc[11*512]);
            float4 o3 = make_float4(xc[12*512],xc[13*512],xc[14*512], xc[15*512]);
            float4* dst = (float4*)(g_xt + (size_t)pid * 64 + cc * 16);
            dst[0] = o0; dst[1] = o1; dst[2] = o2; dst[3] = o3;
        }
    }
    float2* op = (float2*)(g_off + pid * 20);
    #pragma unroll
    for (int j = 0; j < 9; j++) op[j] = unpk2(acc[j]);
}

// ---------------------------------------------------------------------------
// Kernel 2: deformable sampling + DCN conv.  (exact R9 best-known version)
// ---------------------------------------------------------------------------
__global__ __launch_bounds__(256, 2) void k_dcn(float* __restrict__ out) {
    extern __shared__ char smem[];
    float*  sS  = (float*)smem;                     // [2][64][PT]
    float*  sWb = (float*)(smem + 34816);           // [2][4096]
    float*  sRed = (float*)(smem + 34816);          // reduce region (reuses sWb)
    int4*   sPI = (int4*)(smem + 67584);            // [9*64]
    float4* sPF = (float4*)(smem + 76800);          // [9*64]

    const int tid = threadIdx.x;
    // gather mapping
    const int q   = tid & 15;          // channel chunk (4 c's)
    const int sub = tid >> 4;          // pixel-within-pass
    // compute mapping
    const int lane = tid & 31;
    const int wid  = tid >> 5;
    const int Q    = wid & 1;          // o half
    const int ch   = wid >> 1;         // c quarter (16 c's)
    const int pg   = lane & 7;         // pixel quad
    const int osub = (lane >> 3) & 3;
    const int obase = 32*Q + 8*osub;   // 8 o's per thread

    auto stage_w = [&](int k, int buf) {
        const float* src = g_wt + k * 4096 + tid * 4;
        unsigned dst = (unsigned)__cvta_generic_to_shared(sWb + buf * 4096 + tid * 4);
        #pragma unroll
        for (int j = 0; j < 4; j++) {
            asm volatile("cp.async.cg.shared.global [%0], [%1], 16;"
                         :: "r"(dst + j * 4096), "l"(src + j * 1024) : "memory");
        }
        asm volatile("cp.async.commit_group;" ::: "memory");
    };

    float bsum[8], bsq[8];
    #pragma unroll
    for (int j = 0; j < 8; j++) { bsum[j] = 0.f; bsq[j] = 0.f; }

    for (int t = blockIdx.x; t < NTILES; t += DCN_GRID) {
        const int pixbase = t * DCN_PX;

        __syncthreads();   // previous tile's reduce/writes done
        stage_w(0, 0);     // overlap with params computation below

        // ---- sampling params for all (k, px) ----
        for (int tt = tid; tt < 9 * DCN_PX; tt += 256) {
            int k  = tt / DCN_PX;
            int px = tt % DCN_PX;
            int pid = pixbase + px;
            int rem = pid & (HWW - 1);
            int h   = rem / WW;
            int w   = rem % WW;
            int ki = k / 3, kj = k % 3;
            float2 d = *(const float2*)(g_off + pid * 20 + 2 * k);
            float py  = d.x + (float)(h - 1 + ki);
            float pxf = d.y + (float)(w - 1 + kj);
            float y0f = floorf(py), x0f = floorf(pxf);
            float wy = py - y0f, wx = pxf - x0f;
            int y0 = (int)y0f, x0 = (int)x0f;
            bool vy0 = (y0 >= 0)  && (y0 <= HH - 1);
            bool vy1 = (y0 >= -1) && (y0 <= HH - 2);
            bool vx0 = (x0 >= 0)  && (x0 <= WW - 1);
            bool vx1 = (x0 >= -1) && (x0 <= WW - 2);
            float4 wv;
            wv.x = (1.f - wy) * (1.f - wx) * ((vy0 && vx0) ? 1.f : 0.f);
            wv.y = (1.f - wy) * wx         * ((vy0 && vx1) ? 1.f : 0.f);
            wv.z = wy * (1.f - wx)         * ((vy1 && vx0) ? 1.f : 0.f);
            wv.w = wy * wx                 * ((vy1 && vx1) ? 1.f : 0.f);
            int y0c = min(max(y0, 0), HH - 1), y1c = min(max(y0 + 1, 0), HH - 1);
            int x0c = min(max(x0, 0), WW - 1), x1c = min(max(x0 + 1, 0), WW - 1);
            int rowb = (pid >> 14) * HH;
            int4 iv;
            iv.x = ((rowb + y0c) * WW + x0c) * 64;
            iv.y = ((rowb + y0c) * WW + x1c) * 64;
            iv.z = ((rowb + y1c) * WW + x0c) * 64;
            iv.w = ((rowb + y1c) * WW + x1c) * 64;
            sPI[tt] = iv;
            sPF[tt] = wv;
        }
        __syncthreads();   // params visible

        ulonglong2 a[4];
        float4 wvf;

        auto gload = [&](int k, int pp) {
            int px = pp * 16 + sub;
            int4 iv = sPI[k * DCN_PX + px];
            wvf = sPF[k * DCN_PX + px];
            a[0] = *(const ulonglong2*)(g_xt + iv.x + q * 4);
            a[1] = *(const ulonglong2*)(g_xt + iv.y + q * 4);
            a[2] = *(const ulonglong2*)(g_xt + iv.z + q * 4);
            a[3] = *(const ulonglong2*)(g_xt + iv.w + q * 4);
        };
        auto gstore = [&](int pp, float* buf) {
            int px = pp * 16 + sub;
            unsigned long long W0 = splat2(wvf.x);
            unsigned long long W1 = splat2(wvf.y);
            unsigned long long W2 = splat2(wvf.z);
            unsigned long long W3 = splat2(wvf.w);
            unsigned long long lo = mul2(a[0].x, W0);
            lo = fma2(a[1].x, W1, lo);
            lo = fma2(a[2].x, W2, lo);
            lo = fma2(a[3].x, W3, lo);
            unsigned long long hi = mul2(a[0].y, W0);
            hi = fma2(a[1].y, W1, hi);
            hi = fma2(a[2].y, W2, hi);
            hi = fma2(a[3].y, W3, hi);
            float2 f01 = unpk2(lo);
            float2 f23 = unpk2(hi);
            int perm = (((px >> 2) ^ q) + (q >> 3)) & 15;
            float* base = buf + (4*q)*PT + 4*perm + (px & 3);
            base[0]    = f01.x;
            base[PT]   = f01.y;
            base[2*PT] = f23.x;
            base[3*PT] = f23.y;
        };

        unsigned long long acc[4][8];
        #pragma unroll
        for (int i = 0; i < 4; i++)
            #pragma unroll
            for (int j = 0; j < 8; j++) acc[i][j] = 0ULL;

        auto compute_c = [&](int c, const float* buf, const float* wcur) {
            int qc = c >> 2;
            int s  = qc >> 3;
            int permA = ((pg ^ qc) + s) & 15;
            int permB = (((pg + 8) ^ qc) + s) & 15;
            const float* row = buf + c * PT;
            ulonglong2 sA = *(const ulonglong2*)(row + 4*permA);
            ulonglong2 sB = *(const ulonglong2*)(row + 4*permB);
            const float* wp = wcur + c * 64 + obase;
            float4 wa = *(const float4*)(wp);
            float4 wb = *(const float4*)(wp + 4);
            unsigned long long w0 = splat2(wa.x);
            unsigned long long w1 = splat2(wa.y);
            unsigned long long w2 = splat2(wa.z);
            unsigned long long w3 = splat2(wa.w);
            unsigned long long w4 = splat2(wb.x);
            unsigned long long w5 = splat2(wb.y);
            unsigned long long w6 = splat2(wb.z);
            unsigned long long w7 = splat2(wb.w);
            acc[0][0] = fma2(sA.x, w0, acc[0][0]);
            acc[0][1] = fma2(sA.x, w1, acc[0][1]);
            acc[0][2] = fma2(sA.x, w2, acc[0][2]);
            acc[0][3] = fma2(sA.x, w3, acc[0][3]);
            acc[0][4] = fma2(sA.x, w4, acc[0][4]);
            acc[0][5] = fma2(sA.x, w5, acc[0][5]);
            acc[0][6] = fma2(sA.x, w6, acc[0][6]);
            acc[0][7] = fma2(sA.x, w7, acc[0][7]);
            acc[1][0] = fma2(sA.y, w0, acc[1][0]);
            acc[1][1] = fma2(sA.y, w1, acc[1][1]);
            acc[1][2] = fma2(sA.y, w2, acc[1][2]);
            acc[1][3] = fma2(sA.y, w3, acc[1][3]);
            acc[1][4] = fma2(sA.y, w4, acc[1][4]);
            acc[1][5] = fma2(sA.y, w5, acc[1][5]);
            acc[1][6] = fma2(sA.y, w6, acc[1][6]);
            acc[1][7] = fma2(sA.y, w7, acc[1][7]);
            acc[2][0] = fma2(sB.x, w0, acc[2][0]);
            acc[2][1] = fma2(sB.x, w1, acc[2][1]);
            acc[2][2] = fma2(sB.x, w2, acc[2][2]);
            acc[2][3] = fma2(sB.x, w3, acc[2][3]);
            acc[2][4] = fma2(sB.x, w4, acc[2][4]);
            acc[2][5] = fma2(sB.x, w5, acc[2][5]);
            acc[2][6] = fma2(sB.x, w6, acc[2][6]);
            acc[2][7] = fma2(sB.x, w7, acc[2][7]);
            acc[3][0] = fma2(sB.y, w0, acc[3][0]);
            acc[3][1] = fma2(sB.y, w1, acc[3][1]);
            acc[3][2] = fma2(sB.y, w2, acc[3][2]);
            acc[3][3] = fma2(sB.y, w3, acc[3][3]);
            acc[3][4] = fma2(sB.y, w4, acc[3][4]);
            acc[3][5] = fma2(sB.y, w5, acc[3][5]);
            acc[3][6] = fma2(sB.y, w6, acc[3][6]);
            acc[3][7] = fma2(sB.y, w7, acc[3][7]);
        };

        // prologue: gather tap 0
        #pragma unroll
        for (int pp = 0; pp < 4; pp++) {
            gload(0, pp);
            gstore(pp, sS);
        }
        asm volatile("cp.async.wait_group 0;" ::: "memory");
        __syncthreads();

        #pragma unroll 1
        for (int k = 0; k < 9; k++) {
            const float* buf  = sS + (k & 1) * (64 * PT);
            float* nbuf       = sS + ((k + 1) & 1) * (64 * PT);
            const float* wcur = sWb + (k & 1) * 4096;
            if (k < 8) stage_w(k + 1, (k + 1) & 1);
            #pragma unroll
            for (int pp = 0; pp < 4; pp++) {
                if (k < 8) gload(k + 1, pp);
                int c0 = 16 * ch + 4 * pp;
                compute_c(c0 + 0, buf, wcur);
                compute_c(c0 + 1, buf, wcur);
                compute_c(c0 + 2, buf, wcur);
                compute_c(c0 + 3, buf, wcur);
                if (k < 8) gstore(pp, nbuf);
            }
            asm volatile("cp.async.wait_group 0;" ::: "memory");
            __syncthreads();
        }

        // ---- cross-warp c-split reduction (4 -> 1) through smem ----
        float* RA = sRed;              // 4096 floats (16KB)
        float* RB = sRed + 4096;       // 4096 floats

        auto store_acc = [&](float* R) {
            #pragma unroll
            for (int i = 0; i < 16; i++) {
                int pi = i >> 2, j2 = (i & 3) * 2;
                ulonglong2 v;
                v.x = acc[pi][j2];
                v.y = acc[pi][j2 + 1];
                *(ulonglong2*)(R + Q*2048 + i*128 + lane*4) = v;
            }
        };
        auto load_add = [&](const float* R) {
            #pragma unroll
            for (int i = 0; i < 16; i++) {
                int pi = i >> 2, j2 = (i & 3) * 2;
                ulonglong2 v = *(const ulonglong2*)(R + Q*2048 + i*128 + lane*4);
                acc[pi][j2]     = add2(acc[pi][j2], v.x);
                acc[pi][j2 + 1] = add2(acc[pi][j2 + 1], v.y);
            }
        };

        if (ch == 1) store_acc(RA);
        if (ch == 3) store_acc(RB);
        __syncthreads();
        if (ch == 0) load_add(RA);
        if (ch == 2) load_add(RB);
        __syncthreads();
        if (ch == 2) store_acc(RA);
        __syncthreads();
        if (ch == 0) load_add(RA);

        // ---- epilogue: warps 0,1 hold full sums; write NCHW + BN partials --
        if (wid < 2) {
            int b = pixbase >> 14;
            int rem0 = pixbase & (HWW - 1);
            #pragma unroll
            for (int pi = 0; pi < 4; pi++) {
                int pxl = 4*pg + (pi & 1)*2 + (pi >> 1)*32;
                #pragma unroll
                for (int j = 0; j < 8; j++) {
                    int o = obase + j;
                    float2 f = unpk2(acc[pi][j]);
                    *(float2*)(out + (b*64 + o)*HWW + rem0 + pxl) = f;
                    bsum[j] += f.x + f.y;
                    bsq[j]  += f.x*f.x + f.y*f.y;
                }
            }
        }
    }

    // ---- final BN partials: reduce over pg lanes, write per-block ----
    if (wid < 2) {
        #pragma unroll
        for (int j = 0; j < 8; j++) {
            #pragma unroll
            for (int d = 1; d < 8; d <<= 1) {
                bsum[j] += __shfl_xor_sync(0xffffffffu, bsum[j], d);
                bsq[j]  += __shfl_xor_sync(0xffffffffu, bsq[j],  d);
            }
        }
        if (pg == 0) {
            #pragma unroll
            for (int j = 0; j < 8; j++)
                g_part[blockIdx.x * 64 + obase + j] = make_float2(bsum[j], bsq[j]);
        }
    }
}

// ---------------------------------------------------------------------------
// Kernel 3: fused BN finalize + normalize + affine + ReLU.
// 1024 blocks; each covers a quarter-channel (o constant per block).
// Data loads are issued FIRST so the partial reduction hides behind them.
// ---------------------------------------------------------------------------
__global__ __launch_bounds__(256) void k_bnapply(float* __restrict__ out,
                                                 const float* __restrict__ gamma,
                                                 const float* __restrict__ beta) {
    const int tid = threadIdx.x;
    const int o = (blockIdx.x >> 2) & 63;

    // issue this block's data loads first (independent of the reduction)
    int base4 = blockIdx.x * 1024 + tid;
    float4 v[4];
    #pragma unroll
    for (int j = 0; j < 4; j++)
        v[j] = *((const float4*)out + base4 + j * 256);

    // reduce this channel's partials (296 entries) while loads are in flight
    float s = 0.f, qq = 0.f;
    for (int j = tid; j < DCN_GRID; j += 256) {
        float2 p = g_part[j * 64 + o];
        s += p.x; qq += p.y;
    }
    #pragma unroll
    for (int d = 16; d; d >>= 1) {
        s  += __shfl_xor_sync(0xffffffffu, s,  d);
        qq += __shfl_xor_sync(0xffffffffu, qq, d);
    }
    __shared__ float2 red[8];
    __shared__ float2 bc;
    if ((tid & 31) == 0) red[tid >> 5] = make_float2(s, qq);
    __syncthreads();
    if (tid == 0) {
        float ts = 0.f, tq = 0.f;
        #pragma unroll
        for (int i = 0; i < 8; i++) { ts += red[i].x; tq += red[i].y; }
        float inv_n = 1.f / (float)(BB * HWW);
        float mean = ts * inv_n;
        float var  = tq * inv_n - mean * mean;
        float istd = rsqrtf(var + 1e-5f);
        float scale = istd * __ldg(gamma + o);
        float shift = __ldg(beta + o) - mean * scale;
        bc = make_float2(scale, shift);
    }
    __syncthreads();
    const float scale = bc.x;
    const float shift = bc.y;

    // apply + store
    #pragma unroll
    for (int j = 0; j < 4; j++) {
        float4 u = v[j];
        u.x = fmaxf(u.x * scale + shift, 0.f);
        u.y = fmaxf(u.y * scale + shift, 0.f);
        u.z = fmaxf(u.z * scale + shift, 0.f);
        u.w = fmaxf(u.w * scale + shift, 0.f);
        *((float4*)out + base4 + j * 256) = u;
    }
}

// ---------------------------------------------------------------------------
extern "C" void kernel_launch(void* const* d_in, const int* in_sizes, int n_in,
                              void* d_out, int out_size) {
    const float* x     = (const float*)d_in[0];
    const float* ow    = (const float*)d_in[1];
    const float* ob    = (const float*)d_in[2];
    const float* dw    = (const float*)d_in[3];
    const float* gamma = (const float*)d_in[4];
    const float* beta  = (const float*)d_in[5];
    float* out = (float*)d_out;

    k_prep<<<(9*64*64 + 9*64*20 + 255) / 256, 256>>>(dw, ow);

    const int off_smem = (11520 + 8192) * 4;      // 78848
    cudaFuncSetAttribute(k_offconv, cudaFuncAttributeMaxDynamicSharedMemorySize, off_smem);
    k_offconv<<<BB * (HH / 2), 256, off_smem>>>(x, ob);

    const int dcn_smem = 86016;
    cudaFuncSetAttribute(k_dcn, cudaFuncAttributeMaxDynamicSharedMemorySize, dcn_smem);
    k_dcn<<<DCN_GRID, 256, dcn_smem>>>(out);

    k_bnapply<<<1024, 256>>>(out, gamma, beta);
}